// round 3
// baseline (speedup 1.0000x reference)
#include <cuda_runtime.h>
#include <cuda_fp16.h>
#include <math.h>

// Problem constants (CTCLoss_70961449664599): T=2048, B=64, V=512, S=256
#define T_DIM 2048
#define B_DIM 64
#define V_DIM 512
#define S_DIM 256
#define GP2   272               // padded row of halfs: cols 0..255 = symbols, 256 = blank
#define NEG2  (-1.0e30f)
#define LOG2E_F 1.4426950408889634f
#define LN2_F   0.6931471805599453f

// Scratch (allocation-free rule: __device__ globals)
__device__ __half g_G[(size_t)T_DIM * B_DIM * GP2];   // ~71 MB gathered log2-probs (fp16)
__device__ float  g_partial[B_DIM];

__device__ __forceinline__ float ex2f_(float x) {
    float y; asm("ex2.approx.f32 %0, %1;" : "=f"(y) : "f"(x)); return y;
}
__device__ __forceinline__ float lg2f_(float x) {
    float y; asm("lg2.approx.f32 %0, %1;" : "=f"(y) : "f"(x)); return y;
}
// 2-term logaddexp2: 2 MUFU
__device__ __forceinline__ float lse2_(float a, float b) {
    const float m = fmaxf(a, b);
    const float d = -fabsf(a - b);
    return m + lg2f_(1.0f + ex2f_(d));
}

// ---------------------------------------------------------------------------
// Phase 1: per (t,b) row -> lse2 = log2(sum exp(x)); gathered log2-probs (fp16)
//   col j (j<256) = symbol targets[b][j]  (= ext position 2j+1), col 256 = blank
// Grid: (B, T/8), block: 256 threads (8 warps, 1 warp per t-row)
// ---------------------------------------------------------------------------
__global__ __launch_bounds__(256) void ctc_phase1(
    const float* __restrict__ x, const int* __restrict__ targets)
{
    __shared__ float sh_row[8][V_DIM];
    __shared__ int   sh_tgt[S_DIM];

    const int b    = blockIdx.x;
    const int tid  = threadIdx.x;
    const int w    = tid >> 5;
    const int lane = tid & 31;

    sh_tgt[tid] = targets[b * S_DIM + tid];
    __syncthreads();

    const int t = blockIdx.y * 8 + w;
    const float4* row = (const float4*)(x + ((size_t)t * B_DIM + b) * V_DIM);

    float s = 0.0f;
    float4* shv = (float4*)sh_row[w];
#pragma unroll
    for (int k = 0; k < 4; k++) {
        float4 v = row[lane + 32 * k];
        shv[lane + 32 * k] = v;
        s += ex2f_(v.x * LOG2E_F) + ex2f_(v.y * LOG2E_F)
           + ex2f_(v.z * LOG2E_F) + ex2f_(v.w * LOG2E_F);
    }
#pragma unroll
    for (int o = 16; o; o >>= 1) s += __shfl_xor_sync(0xffffffffu, s, o);
    const float lse2v = lg2f_(s);

    __half* gout = g_G + ((size_t)t * B_DIM + b) * GP2;
#pragma unroll
    for (int j = lane; j < 257; j += 32) {
        const int sym = (j < 256) ? sh_tgt[j] : 0;
        gout[j] = __float2half_rn(sh_row[w][sym] * LOG2E_F - lse2v);
    }
}

// ---------------------------------------------------------------------------
// Phase 2: alpha recursion, register-resident.
// 1 block per batch, 256 threads (8 warps). Thread p owns extended positions
// 2p (blank) and 2p+1 (symbol targets[b][p]); tid 255 also owns position 512.
// Neighbor value alpha[2p-1] via shfl_up; 8 floats/step through SMEM at warp
// boundaries; one __syncthreads per step. Log2 domain throughout.
// ---------------------------------------------------------------------------
#define PF 8
__global__ __launch_bounds__(256) void ctc_phase2(
    const int* __restrict__ targets,
    const int* __restrict__ in_len,
    const int* __restrict__ tgt_len)
{
    __shared__ float xhi[2][8];        // per-warp top-odd alpha, double buffered
    __shared__ float sh_alpha[516];    // final readout

    const int b    = blockIdx.x;
    const int tid  = threadIdx.x;
    const int w    = tid >> 5;
    const int lane = tid & 31;
    const int Lin  = in_len[b];        // block-uniform
    const int Lt   = tgt_len[b];
    const int p    = tid;              // pair index 0..255

    // allow2 for odd position 2p+1: symbols are >=1, so just cur != prev
    const int curt  = targets[b * S_DIM + p];
    const int prevt = (p > 0) ? targets[b * S_DIM + p - 1] : 0;
    const bool allow2 = (curt != prevt);

    const size_t stride = (size_t)B_DIM * GP2;
    const __half* gs = g_G + (size_t)b * GP2 + p;     // my symbol column
    const __half* gb = g_G + (size_t)b * GP2 + 256;   // blank column (broadcast)

    // t = 0 init: only positions 0,1 live
    float a_e = (p == 0) ? __half2float(__ldg(gb)) : NEG2;   // pos 2p
    float a_o = (p == 0) ? __half2float(__ldg(gs)) : NEG2;   // pos 2p+1
    float a_x = NEG2;                                        // pos 512 (tid 255)
    if (lane == 31) xhi[0][w] = a_o;
    __syncthreads();

    // prefetch ring (converted to float on load)
    float pf_s[PF], pf_b[PF];
#pragma unroll
    for (int k = 0; k < PF; k++) {
        int tt = 1 + k; if (tt > T_DIM - 1) tt = T_DIM - 1;
        pf_s[k] = __half2float(__ldg(gs + (size_t)tt * stride));
        pf_b[k] = __half2float(__ldg(gb + (size_t)tt * stride));
    }

    int cur = 0;
    for (int t0 = 1; t0 < Lin; t0 += PF) {
        float us[PF], ub[PF];
#pragma unroll
        for (int k = 0; k < PF; k++) { us[k] = pf_s[k]; ub[k] = pf_b[k]; }
#pragma unroll
        for (int k = 0; k < PF; k++) {
            int tt = t0 + PF + k; if (tt > T_DIM - 1) tt = T_DIM - 1;
            pf_s[k] = __half2float(__ldg(gs + (size_t)tt * stride));
            pf_b[k] = __half2float(__ldg(gb + (size_t)tt * stride));
        }
#pragma unroll
        for (int k = 0; k < PF; k++) {
            if (t0 + k >= Lin) break;            // block-uniform
            // neighbor: old alpha[2p-1]
            float a_left = __shfl_up_sync(0xffffffffu, a_o, 1);
            if (lane == 0) a_left = (w > 0) ? xhi[cur][w - 1] : NEG2;

            // even (blank) position 2p: 2-term LSE
            const float ne = lse2_(a_e, a_left) + ub[k];

            // odd (symbol) position 2p+1: 3-term LSE
            const float am2 = allow2 ? a_left : NEG2;
            const float m  = fmaxf(a_o, fmaxf(a_e, am2));
            const float sm = ex2f_(a_o - m) + ex2f_(a_e - m) + ex2f_(am2 - m);
            const float no = m + lg2f_(sm) + us[k];

            // extra position 512 (blank), depends on old a_x and old a_o(511)
            if (tid == 255) a_x = lse2_(a_x, a_o) + ub[k];

            if (lane == 31) xhi[cur ^ 1][w] = no;
            a_e = ne; a_o = no;
            __syncthreads();
            cur ^= 1;
        }
    }

    sh_alpha[2 * p]     = a_e;
    sh_alpha[2 * p + 1] = a_o;
    if (tid == 255) sh_alpha[512] = a_x;
    __syncthreads();

    if (tid == 0) {
        const int idx = 2 * Lt;
        const float la2 = lse2_(sh_alpha[idx], sh_alpha[idx - 1]);
        float loss = -la2 * LN2_F;
        if (!isfinite(loss) || loss > 0.5e30f) loss = 0.0f;   // zero_infinity
        g_partial[b] = loss / (float)Lt;
    }
}

// ---------------------------------------------------------------------------
// Phase 3: mean over batch -> out[0]
// ---------------------------------------------------------------------------
__global__ void ctc_phase3(float* __restrict__ out)
{
    const int lane = threadIdx.x;
    float v = g_partial[lane] + g_partial[lane + 32];
#pragma unroll
    for (int o = 16; o; o >>= 1) v += __shfl_xor_sync(0xffffffffu, v, o);
    if (lane == 0) out[0] = v / (float)B_DIM;
}

// ---------------------------------------------------------------------------
extern "C" void kernel_launch(void* const* d_in, const int* in_sizes, int n_in,
                              void* d_out, int out_size)
{
    const float* x    = (const float*)d_in[0];   // (T, B, V) float32
    const int*   tgt  = (const int*)d_in[1];     // (B, S) int32
    const int*   ilen = (const int*)d_in[2];     // (B,) int32
    const int*   tlen = (const int*)d_in[3];     // (B,) int32
    float*       out  = (float*)d_out;

    dim3 g1(B_DIM, T_DIM / 8);
    ctc_phase1<<<g1, 256>>>(x, tgt);
    ctc_phase2<<<B_DIM, 256>>>(tgt, ilen, tlen);
    ctc_phase3<<<1, 32>>>(out);
}